// round 1
// baseline (speedup 1.0000x reference)
#include <cuda_runtime.h>
#include <math.h>

#define B_ 8
#define E_ 2048
#define H_ 16
#define HD_ 128
#define LOW_ 512
#define SPREV_ 4095
#define S_ 4096
#define KS_ 64           // k-splits for the 2048-deep small GEMMs
#define KCH_ 32          // 2048 / 64
#define SPLITS_ 16       // attention sequence splits
#define CHUNK_ 256       // 4096 / 16
#define TS_ 16           // rows per attention tile

// ---------------- scratch (static device memory; no allocations) ----------------
__device__ float g_Cq[B_*E_];
__device__ float g_Qc[B_*E_];
__device__ float g_qr_pre[B_*HD_];
__device__ float g_qr[B_*HD_];
__device__ float g_qabs[B_*H_*LOW_];
__device__ float g_ckv_new[B_*LOW_];
__device__ float g_kr_new[B_*HD_];
__device__ float g_cos[S_*64];
__device__ float g_sin[S_*64];
__device__ float g_scr[B_*S_];
__device__ float g_part[KS_*B_*E_];
__device__ float g_m[B_*H_*SPLITS_];
__device__ float g_l[B_*H_*SPLITS_];
__device__ float g_ctxp[B_*H_*SPLITS_*LOW_];
__device__ float g_ctxf[B_*H_*LOW_];
__device__ float g_opart[8*B_*H_*HD_];
__device__ float g_o[B_*E_];

// ---------------- rope table: cos/sin of fp32-rounded angle --------------------
__global__ void k_rope() {
    int idx = blockIdx.x * blockDim.x + threadIdx.x;
    if (idx >= S_ * 64) return;
    int s = idx >> 6, i = idx & 63;
    float invf = (float)(1.0 / pow(10000.0, (double)i / 64.0));
    float ang = (float)s * invf;              // fp32 round, like jnp
    double sn, c;
    sincos((double)ang, &sn, &c);
    g_cos[idx] = (float)c;
    g_sin[idx] = (float)sn;
}

// ---------------- generic M=8 GEMM, k-split partials ---------------------------
// Out[b,n] = sum_k X[b,k] * W[k,n], K=2048. grid (ceil(N/256), KS_), 256 thr.
__global__ void k_gemm8(const float* __restrict__ X, const float* __restrict__ W,
                        float* __restrict__ part, int N) {
    __shared__ float xs[B_][KCH_];
    int tid = threadIdx.x;
    int k0 = blockIdx.y * KCH_;
    {
        int b = tid >> 5, kk = tid & 31;   // 256 = 8*32
        xs[b][kk] = X[b * E_ + k0 + kk];
    }
    __syncthreads();
    int n = blockIdx.x * 256 + tid;
    if (n < N) {
        float acc[B_] = {0.f,0.f,0.f,0.f,0.f,0.f,0.f,0.f};
        const float* wp = W + (size_t)k0 * N + n;
        #pragma unroll
        for (int kk = 0; kk < KCH_; ++kk) {
            float wv = wp[(size_t)kk * N];
            #pragma unroll
            for (int b = 0; b < B_; ++b) acc[b] = fmaf(xs[b][kk], wv, acc[b]);
        }
        float* pp = part + (size_t)(blockIdx.y * B_) * N + n;
        #pragma unroll
        for (int b = 0; b < B_; ++b) pp[(size_t)b * N] = acc[b];
    }
}

__global__ void k_reduce8(const float* __restrict__ part, float* __restrict__ out, int N) {
    int idx = blockIdx.x * 256 + threadIdx.x;
    if (idx >= B_ * N) return;
    int b = idx / N, n = idx - b * N;
    float acc = 0.f;
    #pragma unroll 8
    for (int s = 0; s < KS_; ++s) acc += part[(size_t)(s * B_ + b) * N + n];
    out[idx] = acc;
}

// ---------------- rope the query rotary part at position S-1 -------------------
__global__ void k_ropeq() {
    int b = blockIdx.x, i = threadIdx.x;   // 64 threads
    float q1 = g_qr_pre[b * HD_ + i];
    float q2 = g_qr_pre[b * HD_ + i + 64];
    float c = g_cos[(S_ - 1) * 64 + i];
    float s = g_sin[(S_ - 1) * 64 + i];
    g_qr[b * HD_ + i]       = q1 * c - q2 * s;
    g_qr[b * HD_ + i + 64]  = q1 * s + q2 * c;
}

// ---------------- absorbed query: q_abs[b,h,low] = Qc[b,h,:] . Wuk[low,h,:] ----
__global__ void k_qabs(const float* __restrict__ FU) {
    int h = blockIdx.y;
    int w = threadIdx.x >> 5, lane = threadIdx.x & 31;
    int low = blockIdx.x * 8 + w;
    float4 w4 = *(const float4*)(FU + (size_t)low * (2 * E_) + h * HD_ + lane * 4);
    #pragma unroll
    for (int b = 0; b < B_; ++b) {
        float4 q4 = *(const float4*)(g_Qc + b * E_ + h * HD_ + lane * 4);
        float acc = w4.x * q4.x + w4.y * q4.y + w4.z * q4.z + w4.w * q4.w;
        #pragma unroll
        for (int off = 16; off; off >>= 1) acc += __shfl_xor_sync(0xffffffffu, acc, off);
        if (lane == 0) g_qabs[(b * H_ + h) * LOW_ + low] = acc;
    }
}

// ---------------- rotary scores: scr[b,s] = rope(kr[b,s],s) . qr_roped[b] ------
__global__ void k_scr(const float* __restrict__ krc) {
    int gw = blockIdx.x * 8 + (threadIdx.x >> 5);
    int lane = threadIdx.x & 31;
    int b = gw >> 12;
    int s = gw & (S_ - 1);
    const float* kr = (s < SPREV_) ? (krc + ((size_t)b * SPREV_ + s) * HD_)
                                   : (g_kr_new + b * HD_);
    float k1a = kr[lane], k1b = kr[lane + 32], k2a = kr[lane + 64], k2b = kr[lane + 96];
    float ca = g_cos[s * 64 + lane], cb = g_cos[s * 64 + lane + 32];
    float sa = g_sin[s * 64 + lane], sb = g_sin[s * 64 + lane + 32];
    const float* q = g_qr + b * HD_;
    float q1a = q[lane], q1b = q[lane + 32], q2a = q[lane + 64], q2b = q[lane + 96];
    float acc = ca * (q1a * k1a + q2a * k2a) + sa * (q2a * k1a - q1a * k2a)
              + cb * (q1b * k1b + q2b * k2b) + sb * (q2b * k1b - q1b * k2b);
    #pragma unroll
    for (int off = 16; off; off >>= 1) acc += __shfl_xor_sync(0xffffffffu, acc, off);
    if (lane == 0) g_scr[b * S_ + s] = acc;
}

// ---------------- flash attention in latent space ------------------------------
// grid (SPLITS_, B_), 512 threads. warp w = head w (scores); thread t = low t (ctx).
__global__ void __launch_bounds__(512, 1) k_attn(const float* __restrict__ ckv) {
    __shared__ float cvs[TS_][LOW_];
    __shared__ float p_s[H_][TS_];
    __shared__ float alpha_s[H_];
    int split = blockIdx.x, b = blockIdx.y;
    int tid = threadIdx.x, w = tid >> 5, lane = tid & 31;

    float q[16];
    {
        const float* qa = g_qabs + (b * H_ + w) * LOW_;
        #pragma unroll
        for (int g = 0; g < 4; ++g) {
            float4 t = *(const float4*)(qa + g * 128 + lane * 4);
            q[g * 4 + 0] = t.x; q[g * 4 + 1] = t.y;
            q[g * 4 + 2] = t.z; q[g * 4 + 3] = t.w;
        }
    }
    float m = -1e30f, l = 0.f;
    float ctx[16];
    #pragma unroll
    for (int h = 0; h < H_; ++h) ctx[h] = 0.f;

    int s0 = split * CHUNK_;
    for (int tile = 0; tile < CHUNK_ / TS_; ++tile) {
        int sb = s0 + tile * TS_;
        __syncthreads();   // protect cvs/p_s reuse from previous tile
        #pragma unroll
        for (int i = 0; i < 4; ++i) {
            int g = tid + 512 * i;
            int r = g >> 7;
            int c4 = (g & 127) << 2;
            int sidx = sb + r;
            const float* src = (sidx < SPREV_)
                ? (ckv + ((size_t)b * SPREV_ + sidx) * LOW_ + c4)
                : (g_ckv_new + b * LOW_ + c4);
            *(float4*)&cvs[r][c4] = *(const float4*)src;
        }
        __syncthreads();

        // ---- scores for head w (one warp per head) ----
        float p[TS_];
        {
            float sc[TS_];
            #pragma unroll
            for (int r = 0; r < TS_; ++r) {
                float acc = 0.f;
                #pragma unroll
                for (int g = 0; g < 4; ++g) {
                    float4 c = *(const float4*)&cvs[r][g * 128 + lane * 4];
                    acc = fmaf(q[g * 4 + 0], c.x, acc);
                    acc = fmaf(q[g * 4 + 1], c.y, acc);
                    acc = fmaf(q[g * 4 + 2], c.z, acc);
                    acc = fmaf(q[g * 4 + 3], c.w, acc);
                }
                #pragma unroll
                for (int off = 16; off; off >>= 1) acc += __shfl_xor_sync(0xffffffffu, acc, off);
                sc[r] = acc;
            }
            float mt = -1e30f;
            #pragma unroll
            for (int r = 0; r < TS_; ++r) {
                sc[r] = (sc[r] + g_scr[b * S_ + sb + r]) * 0.0625f;  // / sqrt(256)
                mt = fmaxf(mt, sc[r]);
            }
            float mn = fmaxf(m, mt);
            float al = __expf(m - mn);
            float ps = 0.f;
            #pragma unroll
            for (int r = 0; r < TS_; ++r) { p[r] = __expf(sc[r] - mn); ps += p[r]; }
            l = l * al + ps;
            m = mn;
            if (lane == 0) {
                alpha_s[w] = al;
                #pragma unroll
                for (int r = 0; r < TS_; ++r) p_s[w][r] = p[r];
            }
        }
        __syncthreads();

        // ---- ctx update: thread owns low = tid, accumulates all 16 heads ----
        float cv[TS_];
        #pragma unroll
        for (int r = 0; r < TS_; ++r) cv[r] = cvs[r][tid];
        #pragma unroll
        for (int h = 0; h < H_; ++h) {
            float c = ctx[h] * alpha_s[h];
            #pragma unroll
            for (int r = 0; r < TS_; ++r) c = fmaf(p_s[h][r], cv[r], c);
            ctx[h] = c;
        }
    }

    #pragma unroll
    for (int h = 0; h < H_; ++h)
        g_ctxp[(size_t)((b * H_ + h) * SPLITS_ + split) * LOW_ + tid] = ctx[h];
    if (lane == 0) {
        g_m[(b * H_ + w) * SPLITS_ + split] = m;
        g_l[(b * H_ + w) * SPLITS_ + split] = l;
    }
}

// ---------------- combine split partials + normalize ---------------------------
__global__ void k_combine() {
    int bh = blockIdx.x;        // 128
    int tid = threadIdx.x;      // 512
    float mg = -1e30f;
    #pragma unroll
    for (int s = 0; s < SPLITS_; ++s) mg = fmaxf(mg, g_m[bh * SPLITS_ + s]);
    float L = 0.f, acc = 0.f;
    #pragma unroll
    for (int s = 0; s < SPLITS_; ++s) {
        float wgt = __expf(g_m[bh * SPLITS_ + s] - mg);
        L += g_l[bh * SPLITS_ + s] * wgt;
        acc += g_ctxp[(size_t)(bh * SPLITS_ + s) * LOW_ + tid] * wgt;
    }
    g_ctxf[bh * LOW_ + tid] = acc / L;
}

// ---------------- V projection: o[b,h,d] = ctxf[b,h,:] . Wv[:,h,d] -------------
__global__ void k_vproj(const float* __restrict__ FU) {
    int h = blockIdx.x, ls = blockIdx.y;   // 16 x 8
    int d = threadIdx.x;                   // 128
    __shared__ float cf[B_][64];
    #pragma unroll
    for (int j = 0; j < 4; ++j) {
        int i = d + 128 * j;
        int bb = i >> 6, lo = i & 63;
        cf[bb][lo] = g_ctxf[(bb * H_ + h) * LOW_ + ls * 64 + lo];
    }
    __syncthreads();
    float acc[B_] = {0.f,0.f,0.f,0.f,0.f,0.f,0.f,0.f};
    #pragma unroll 8
    for (int lo = 0; lo < 64; ++lo) {
        float wv = FU[(size_t)(ls * 64 + lo) * (2 * E_) + E_ + h * HD_ + d];
        #pragma unroll
        for (int b = 0; b < B_; ++b) acc[b] = fmaf(cf[b][lo], wv, acc[b]);
    }
    #pragma unroll
    for (int b = 0; b < B_; ++b)
        g_opart[((ls * B_ + b) * H_ + h) * HD_ + d] = acc[b];
}

__global__ void k_reduceo() {
    int idx = blockIdx.x * 256 + threadIdx.x;
    if (idx >= B_ * E_) return;
    int b = idx >> 11, e = idx & 2047;
    int h = e >> 7, d = e & 127;
    float acc = 0.f;
    #pragma unroll
    for (int ls = 0; ls < 8; ++ls)
        acc += g_opart[((ls * B_ + b) * H_ + h) * HD_ + d];
    g_o[idx] = acc;
}

// -------------------------------------------------------------------------------
extern "C" void kernel_launch(void* const* d_in, const int* in_sizes, int n_in,
                              void* d_out, int out_size) {
    const float* x    = (const float*)d_in[0];
    const float* ckv  = (const float*)d_in[1];
    const float* krc  = (const float*)d_in[2];
    const float* Wdq  = (const float*)d_in[3];
    const float* Wuq  = (const float*)d_in[4];
    const float* Wqr  = (const float*)d_in[5];
    const float* Wdkv = (const float*)d_in[6];
    const float* Wkr  = (const float*)d_in[7];
    const float* FU   = (const float*)d_in[8];
    const float* Wo   = (const float*)d_in[9];
    float* out = (float*)d_out;

    float *pCq, *pQc, *pPart, *pQrp, *pCkvn, *pKrn, *pO;
    cudaGetSymbolAddress((void**)&pCq,   g_Cq);
    cudaGetSymbolAddress((void**)&pQc,   g_Qc);
    cudaGetSymbolAddress((void**)&pPart, g_part);
    cudaGetSymbolAddress((void**)&pQrp,  g_qr_pre);
    cudaGetSymbolAddress((void**)&pCkvn, g_ckv_new);
    cudaGetSymbolAddress((void**)&pKrn,  g_kr_new);
    cudaGetSymbolAddress((void**)&pO,    g_o);

    k_rope<<<(S_ * 64) / 256, 256>>>();

    // Cq = x @ Wdq
    k_gemm8<<<dim3(8, KS_), 256>>>(x, Wdq, pPart, E_);
    k_reduce8<<<(B_ * E_ + 255) / 256, 256>>>(pPart, pCq, E_);
    // ckv_new = x @ Wdkv
    k_gemm8<<<dim3(2, KS_), 256>>>(x, Wdkv, pPart, LOW_);
    k_reduce8<<<(B_ * LOW_ + 255) / 256, 256>>>(pPart, pCkvn, LOW_);
    // kr_new = x @ Wkr
    k_gemm8<<<dim3(1, KS_), 256>>>(x, Wkr, pPart, HD_);
    k_reduce8<<<(B_ * HD_ + 255) / 256, 256>>>(pPart, pKrn, HD_);
    // Qc = Cq @ Wuq
    k_gemm8<<<dim3(8, KS_), 256>>>(pCq, Wuq, pPart, E_);
    k_reduce8<<<(B_ * E_ + 255) / 256, 256>>>(pPart, pQc, E_);
    // qr_pre = Cq @ Wqr ; rope at pos S-1
    k_gemm8<<<dim3(1, KS_), 256>>>(pCq, Wqr, pPart, HD_);
    k_reduce8<<<(B_ * HD_ + 255) / 256, 256>>>(pPart, pQrp, HD_);
    k_ropeq<<<B_, 64>>>();

    k_qabs<<<dim3(64, 16), 256>>>(FU);
    k_scr<<<4096, 256>>>(krc);
    k_attn<<<dim3(SPLITS_, B_), 512>>>(ckv);
    k_combine<<<128, 512>>>();
    k_vproj<<<dim3(16, 8), 128>>>(FU);
    k_reduceo<<<(B_ * E_ + 255) / 256, 256>>>();

    // out = o @ Wo
    k_gemm8<<<dim3(8, KS_), 256>>>(pO, Wo, pPart, E_);
    k_reduce8<<<(B_ * E_ + 255) / 256, 256>>>(pPart, out, E_);
    (void)in_sizes; (void)n_in; (void)out_size;
}